// round 13
// baseline (speedup 1.0000x reference)
#include <cuda_runtime.h>
#include <cuda_bf16.h>
#include <math_constants.h>

// Problem constants (fixed shapes)
#define B_   8
#define C_   21
#define H_   512
#define W_   512
#define HW_  (H_ * W_)           // 262144 = 2^18
#define HW_SHIFT 18
#define NPIX (B_ * HW_)          // 2097152
#define MAX_M 0.5f
#define S_    30.0f

#define HGRID 1184               // 148 SMs * 8 CTAs: one full wave
#define LGRID (NPIX / 256)       // 8192 blocks, 1 pixel/thread (proven R3)
#define SUB   4                  // sub-bins per class per warp (conflict spread)

// Persistent state (device globals; each kernel's last block self-resets its
// own state, so every graph replay starts clean).
__device__ float        g_counts[C_];
__device__ float        g_mlist[C_];
__device__ double       g_loss;
__device__ unsigned int g_hdone;
__device__ unsigned int g_ldone;

// ---------------------------------------------------------------------------
// Kernel 1: histogram + m_list, one launch.
// Full-chip grid, grid-strided int4 loads, per-warp smem histograms with
// 4-way sub-binning (sh[wid][c*4 + (lane&3)]) so same-class lanes hit
// different addresses -> ATOMS serialization cut ~4x vs single-bin rows.
// The LAST block to finish (done-counter) computes m_list from the global
// counts, then resets the counts and the counter.
// ---------------------------------------------------------------------------
__global__ __launch_bounds__(256) void hist_mlist_kernel(const int* __restrict__ target) {
    __shared__ int sh[8][C_ * SUB];
    __shared__ int s_last;

    const int tid  = threadIdx.x;
    const int wid  = tid >> 5;
    const int lane = tid & 31;
    const int sub  = lane & (SUB - 1);

    for (int i = tid; i < 8 * C_ * SUB; i += 256) (&sh[0][0])[i] = 0;
    __syncthreads();

    const int4* t4 = reinterpret_cast<const int4*>(target);
    const int   n4 = NPIX / 4;
    for (int i = blockIdx.x * 256 + tid; i < n4; i += HGRID * 256) {
        int4 a = __ldg(t4 + i);
        atomicAdd(&sh[wid][a.x * SUB + sub], 1);
        atomicAdd(&sh[wid][a.y * SUB + sub], 1);
        atomicAdd(&sh[wid][a.z * SUB + sub], 1);
        atomicAdd(&sh[wid][a.w * SUB + sub], 1);
    }
    __syncthreads();

    if (tid < C_) {
        int s = 0;
#pragma unroll
        for (int w = 0; w < 8; w++)
#pragma unroll
            for (int k = 0; k < SUB; k++)
                s += sh[w][tid * SUB + k];
        if (s) atomicAdd(&g_counts[tid], (float)s);   // exact: totals < 2^24
    }

    if (tid == 0) {
        __threadfence();   // this block's count atomics visible before arrive
        s_last = (atomicAdd(&g_hdone, 1u) == HGRID - 1) ? 1 : 0;
    }
    __syncthreads();

    if (s_last && wid == 0) {
        // All blocks' atomics are visible (each fenced before its arrive).
        float mi = 0.0f, m = -CUDART_INF_F;
        if (lane < C_) {
            float c = atomicAdd(&g_counts[lane], 0.0f);  // coherent read
            mi = rsqrtf(sqrtf(c + 1e-4f));
            m  = mi;
        }
#pragma unroll
        for (int o = 16; o > 0; o >>= 1)
            m = fmaxf(m, __shfl_xor_sync(0xffffffffu, m, o));
        if (lane < C_) {
            g_mlist[lane]  = mi * (MAX_M / m);
            g_counts[lane] = 0.0f;              // reset for next replay
        }
        if (lane == 0) { __threadfence(); g_hdone = 0u; }
    }
}

// ---------------------------------------------------------------------------
// Kernel 2: LDAM NLL — the exact R3 body (best measured: 33.1us, DRAM 71.7%,
// occ 91.4%): 1 pixel/thread, single pass, in-loop margin with static
// indexing so v[] stays in registers. Finalize fused via done-counter;
// last block writes the mean and self-resets g_loss / g_ldone.
// ---------------------------------------------------------------------------
__global__ __launch_bounds__(256) void loss_kernel(const float* __restrict__ pred,
                                                   const int*   __restrict__ target,
                                                   float*       __restrict__ out) {
    int n  = blockIdx.x * 256 + threadIdx.x;   // exact grid: n < NPIX
    int b  = n >> HW_SHIFT;
    int hw = n & (HW_ - 1);
    const float* base = pred + (size_t)(b * C_) * HW_ + hw;

    int   l = target[n];
    float m = g_mlist[l];

    float v[C_];
    float maxv = -CUDART_INF_F;
    float vl   = 0.0f;
#pragma unroll
    for (int c = 0; c < C_; c++) {
        float x = __ldg(base + (size_t)c * HW_);
        if (c == l) x -= m;
        v[c] = x;
        maxv = fmaxf(maxv, x);
        if (c == l) vl = x;
    }

    float s = 0.0f;
#pragma unroll
    for (int c = 0; c < C_; c++)
        s += __expf(S_ * (v[c] - maxv));

    float nll = __logf(s) + S_ * (maxv - vl);

    // Warp reduce, cross-warp via smem, one f64 atomic per block.
#pragma unroll
    for (int o = 16; o > 0; o >>= 1)
        nll += __shfl_xor_sync(0xffffffffu, nll, o);

    __shared__ float warp_sums[8];
    int lane = threadIdx.x & 31;
    int wid  = threadIdx.x >> 5;
    if (lane == 0) warp_sums[wid] = nll;
    __syncthreads();

    if (wid == 0) {
        float x = (lane < 8) ? warp_sums[lane] : 0.0f;
#pragma unroll
        for (int o = 4; o > 0; o >>= 1)
            x += __shfl_xor_sync(0xffffffffu, x, o);
        if (lane == 0) {
            atomicAdd(&g_loss, (double)x);
            __threadfence();
            unsigned int done = atomicAdd(&g_ldone, 1u);
            if (done == (unsigned int)(LGRID - 1)) {
                double total = atomicAdd(&g_loss, 0.0);
                out[0] = (float)(total * (1.0 / (double)NPIX));
                g_loss = 0.0;                   // reset for next replay
                __threadfence();
                g_ldone = 0u;
            }
        }
    }
}

// ---------------------------------------------------------------------------
extern "C" void kernel_launch(void* const* d_in, const int* in_sizes, int n_in,
                              void* d_out, int out_size) {
    const float* pred   = (const float*)d_in[0];
    const int*   target = (const int*)d_in[1];
    float*       out    = (float*)d_out;

    hist_mlist_kernel<<<HGRID, 256>>>(target);
    loss_kernel<<<LGRID, 256>>>(pred, target, out);
}